// round 10
// baseline (speedup 1.0000x reference)
#include <cuda_runtime.h>
#include <math_constants.h>

#define BB 8
#define HH 3
#define PP 4096
#define NPTS (BB * PP)
#define GD 32
#define GD2 (GD * GD)
#define NC (GD * GD * GD)
#define NNT 128
#define NNB (NPTS / NNT)        // 256 blocks / partials

// sorted points (x,y,z,|q|^2) + per-head plane distances, grid CSR, partials
__device__ float4 g_pts4[NPTS];
__device__ float  g_qd0[NPTS], g_qd1[NPTS], g_qd2[NPTS];
__device__ int    g_cellstart[BB][NC + 1];
__device__ int    g_work[2][BB][NC];     // [0]=hist, [1]=scatter counters
__device__ float  g_grid[BB][4];         // lo, inv, cellsize, hi
__device__ float  g_partial[NNB];

// normalized plane normals + offset for batch b (fp32, Newton-refined rsqrt)
__device__ __forceinline__ void load_normals(const float* __restrict__ planes,
                                             int b, float nx[HH], float ny[HH],
                                             float nz[HH], float nc[HH]) {
#pragma unroll
    for (int h = 0; h < HH; h++) {
        const float* pl = planes + (b * HH + h) * 4;
        float x = pl[0], y = pl[1], z = pl[2];
        float nn = x * x + y * y + z * z;
        float inv = rsqrtf(nn);
        inv = inv * (1.5f - 0.5f * nn * inv * inv);
        nx[h] = x * inv; ny[h] = y * inv; nz[h] = z * inv; nc[h] = pl[3];
    }
}

// ---------------------------------------------------------------------------
// Sort: one block per batch. bbox -> uniform 32^3 grid -> counting sort.
// Emits sorted float4 (x,y,z,w) + per-head plane distances + cell CSR.
// ---------------------------------------------------------------------------
__global__ __launch_bounds__(512)
void sort_kernel(const float* __restrict__ planes,
                 const float* __restrict__ pts) {
    __shared__ float s_lo[512], s_hi[512];
    __shared__ int   s_a[512], s_b[512];
    __shared__ float s_g[2];
    const int b = blockIdx.x, t = threadIdx.x;

    float X[8], Y[8], Z[8];
    float lo = CUDART_INF_F, hi = -CUDART_INF_F;
#pragma unroll
    for (int k = 0; k < 8; k++) {
        const float* p = pts + (b * PP + k * 512 + t) * 3;
        X[k] = p[0]; Y[k] = p[1]; Z[k] = p[2];
        lo = fminf(lo, fminf(X[k], fminf(Y[k], Z[k])));
        hi = fmaxf(hi, fmaxf(X[k], fmaxf(Y[k], Z[k])));
    }
    s_lo[t] = lo; s_hi[t] = hi;
    __syncthreads();
    for (int off = 256; off > 0; off >>= 1) {
        if (t < off) {
            s_lo[t] = fminf(s_lo[t], s_lo[t + off]);
            s_hi[t] = fmaxf(s_hi[t], s_hi[t + off]);
        }
        __syncthreads();
    }
    if (t == 0) {
        float l = s_lo[0] - 1e-3f, h = s_hi[0] + 1e-3f;
        float inv = (float)GD / (h - l);
        s_g[0] = l; s_g[1] = inv;
        g_grid[b][0] = l; g_grid[b][1] = inv;
        g_grid[b][2] = (h - l) / (float)GD; g_grid[b][3] = h;
    }
    __syncthreads();
    const float gl = s_g[0], gin = s_g[1];

    int C[8];
#pragma unroll
    for (int k = 0; k < 8; k++) {
        int cx = min(GD - 1, max(0, (int)((X[k] - gl) * gin)));
        int cy = min(GD - 1, max(0, (int)((Y[k] - gl) * gin)));
        int cz = min(GD - 1, max(0, (int)((Z[k] - gl) * gin)));
        C[k] = cx * GD2 + cy * GD + cz;
        atomicAdd(&g_work[0][b][C[k]], 1);
    }
    __syncthreads();   // block-scope visibility of our own global atomics

    // scan 32768 bins: 64 serial per thread + Hillis-Steele over 512 partials
    const int BPT = NC / 512;
    const int base = t * BPT;
    int sum = 0;
    for (int i = 0; i < BPT; i++) sum += g_work[0][b][base + i];
    s_a[t] = sum;
    __syncthreads();
    int* src = s_a; int* dst = s_b;
    for (int off = 1; off < 512; off <<= 1) {
        int v = src[t];
        if (t >= off) v += src[t - off];
        dst[t] = v;
        __syncthreads();
        int* tmp = src; src = dst; dst = tmp;
    }
    int run = src[t] - sum;    // exclusive prefix of this thread's group
    for (int i = 0; i < BPT; i++) {
        g_cellstart[b][base + i] = run;
        run += g_work[0][b][base + i];
    }
    if (t == 0) g_cellstart[b][NC] = PP;
    __syncthreads();

    float nx[HH], ny[HH], nz[HH], nco[HH];
    load_normals(planes, b, nx, ny, nz, nco);

#pragma unroll
    for (int k = 0; k < 8; k++) {
        int pos = g_cellstart[b][C[k]] + atomicAdd(&g_work[1][b][C[k]], 1);
        int gidx = b * PP + pos;
        float x = X[k], y = Y[k], z = Z[k];
        g_pts4[gidx] = make_float4(x, y, z, x * x + y * y + z * z);
        g_qd0[gidx] = nx[0] * x + ny[0] * y + nz[0] * z + nco[0];
        g_qd1[gidx] = nx[1] * x + ny[1] * y + nz[1] * z + nco[1];
        g_qd2[gidx] = nx[2] * x + ny[2] * y + nz[2] * z + nco[2];
    }
}

// ---------------------------------------------------------------------------
// NN: one thread per sorted point. Per head: query r = reflect(p); expanding
// Chebyshev ring search around clamp(r)'s cell. Stop when
//   best_dist^2 <= |r - clamp(r)|^2 + margin(m)^2   (projection inequality).
// Exact: every unscanned cell is provably farther. Value = min (order-free).
// ---------------------------------------------------------------------------
__global__ __launch_bounds__(NNT)
void nn_kernel(const float* __restrict__ planes) {
    __shared__ float red[NNT];
    const int gidx = blockIdx.x * NNT + threadIdx.x;
    const int b = gidx / PP;

    float nx[HH], ny[HH], nz[HH], nco[HH];
    load_normals(planes, b, nx, ny, nz, nco);

    const float4 p = g_pts4[gidx];
    const float dh[HH] = {g_qd0[gidx], g_qd1[gidx], g_qd2[gidx]};
    const float gl = g_grid[b][0], gin = g_grid[b][1];
    const float gcs = g_grid[b][2], gh = g_grid[b][3];
    const int* __restrict__ cst = g_cellstart[b];
    const float4* __restrict__ qs = g_pts4 + b * PP;

    float ssum = 0.0f;

#pragma unroll
    for (int h = 0; h < HH; h++) {
        const float rx = p.x - 2.0f * dh[h] * nx[h];
        const float ry = p.y - 2.0f * dh[h] * ny[h];
        const float rz = p.z - 2.0f * dh[h] * nz[h];
        const float r2 = rx * rx + ry * ry + rz * rz;
        const float m2x = -2.0f * rx, m2y = -2.0f * ry, m2z = -2.0f * rz;

        // clamp query into grid box; o2 = |r - r'|^2
        const float cxf = fminf(fmaxf(rx, gl), gh);
        const float cyf = fminf(fmaxf(ry, gl), gh);
        const float czf = fminf(fmaxf(rz, gl), gh);
        const float dox = rx - cxf, doy = ry - cyf, doz = rz - czf;
        const float o2 = dox * dox + doy * doy + doz * doz;

        const int cx = min(GD - 1, max(0, (int)((cxf - gl) * gin)));
        const int cy = min(GD - 1, max(0, (int)((cyf - gl) * gin)));
        const int cz = min(GD - 1, max(0, (int)((czf - gl) * gin)));

        float best = CUDART_INF_F;   // min of (w_q - 2 r.q); dist^2 = best + r2

        for (int m = 0; m < GD; m++) {
            const int x0 = max(cx - m, 0), x1 = min(cx + m, GD - 1);
            const int y0 = max(cy - m, 0), y1 = min(cy + m, GD - 1);
            const int z0 = max(cz - m, 0), z1 = min(cz + m, GD - 1);
            for (int ix = x0; ix <= x1; ix++) {
                const bool fx = (ix == cx - m) || (ix == cx + m);
                for (int iy = y0; iy <= y1; iy++) {
                    const int rowb = ix * GD2 + iy * GD;
                    if (fx || iy == cy - m || iy == cy + m) {
                        // full contiguous z-run
                        const int s0 = cst[rowb + z0];
                        const int s1 = cst[rowb + z1 + 1];
                        for (int q = s0; q < s1; q++) {
                            float4 f = qs[q];
                            float acc = fmaf(m2x, f.x, f.w);
                            acc = fmaf(m2y, f.y, acc);
                            acc = fmaf(m2z, f.z, acc);
                            best = fminf(best, acc);
                        }
                    } else {
                        const int zl = cz - m;
                        if (zl >= 0) {
                            const int s0 = cst[rowb + zl], s1 = cst[rowb + zl + 1];
                            for (int q = s0; q < s1; q++) {
                                float4 f = qs[q];
                                float acc = fmaf(m2x, f.x, f.w);
                                acc = fmaf(m2y, f.y, acc);
                                acc = fmaf(m2z, f.z, acc);
                                best = fminf(best, acc);
                            }
                        }
                        const int zh = cz + m;
                        if (zh < GD) {
                            const int s0 = cst[rowb + zh], s1 = cst[rowb + zh + 1];
                            for (int q = s0; q < s1; q++) {
                                float4 f = qs[q];
                                float acc = fmaf(m2x, f.x, f.w);
                                acc = fmaf(m2y, f.y, acc);
                                acc = fmaf(m2z, f.z, acc);
                                best = fminf(best, acc);
                            }
                        }
                    }
                }
            }
            // stopping bound: margin of r' inside expanded box B_m
            float mg = fminf(cxf - (gl + (float)(cx - m) * gcs),
                             (gl + (float)(cx + m + 1) * gcs) - cxf);
            mg = fminf(mg, fminf(cyf - (gl + (float)(cy - m) * gcs),
                                 (gl + (float)(cy + m + 1) * gcs) - cyf));
            mg = fminf(mg, fminf(czf - (gl + (float)(cz - m) * gcs),
                                 (gl + (float)(cz + m + 1) * gcs) - czf));
            if (mg > 0.0f) {
                const float bd = fmaxf(best + r2, 0.0f);
                if (bd <= o2 + mg * mg) break;
            }
        }
        ssum += fmaxf(best + r2, 0.0f);
    }

    red[threadIdx.x] = ssum;
    __syncthreads();
#pragma unroll
    for (int off = NNT / 2; off > 0; off >>= 1) {
        if (threadIdx.x < off) red[threadIdx.x] += red[threadIdx.x + off];
        __syncthreads();
    }
    if (threadIdx.x == 0) g_partial[blockIdx.x] = red[0];
}

// ---------------------------------------------------------------------------
// Finalize: tree-reduce 256 partials + per-batch reg loss.
// ---------------------------------------------------------------------------
__global__ __launch_bounds__(256)
void finalize_kernel(const float* __restrict__ planes,
                     float* __restrict__ out) {
    __shared__ float red[256];
    __shared__ float regs[BB];
    const int t = threadIdx.x;

    red[t] = g_partial[t];
    __syncthreads();
#pragma unroll
    for (int off = 128; off > 0; off >>= 1) {
        if (t < off) red[t] += red[t + off];
        __syncthreads();
    }

    if (t < BB) {
        float nx[HH], ny[HH], nz[HH], nco[HH];
        load_normals(planes, t, nx, ny, nz, nco);
        float acc = 0.0f;
#pragma unroll
        for (int i = 0; i < HH; i++)
#pragma unroll
            for (int j = 0; j < HH; j++) {
                float g = nx[i] * nx[j] + ny[i] * ny[j] + nz[i] * nz[j]
                        - (i == j ? 1.0f : 0.0f);
                acc += g * g;
            }
        regs[t] = sqrtf(acc);
    }
    __syncthreads();

    if (t == 0) {
        float reg = 0.0f;
#pragma unroll
        for (int b = 0; b < BB; b++) reg += regs[b];
        // cham_x == cham_y by reflection symmetry -> factor 2
        float refl = 2.0f * red[0] / (float)(BB * PP);
        out[0] = refl + 25.0f * reg;
    }
}

// ---------------------------------------------------------------------------
extern "C" void kernel_launch(void* const* d_in, const int* in_sizes, int n_in,
                              void* d_out, int out_size) {
    const float* planes = (const float*)d_in[0];   // (8, 3, 4)
    const float* pts    = (const float*)d_in[1];   // (8, 4096, 3)
    // d_in[2], d_in[3] (voxel/cp grids) are unused by the reference.

    void* wp = nullptr;
    cudaGetSymbolAddress(&wp, g_work);
    cudaMemsetAsync(wp, 0, sizeof(int) * 2 * BB * NC);

    sort_kernel<<<BB, 512>>>(planes, pts);
    nn_kernel<<<NNB, NNT>>>(planes);
    finalize_kernel<<<1, 256>>>(planes, (float*)d_out);
}

// round 11
// speedup vs baseline: 23.5393x; 23.5393x over previous
#include <cuda_runtime.h>
#include <math_constants.h>

// Problem shape
#define BB 8
#define HH 3
#define PP 4096
#define NPTS (BB * PP)
#define ISUP 512                 // I-tile (register side)
#define JCH  256                 // J-tile (smem side)
#define NPAIR (JCH / 2)          // 128 packed J-pairs
#define TP 128                   // threads per block
#define IK 4                     // I points per thread
#define BLKB 72                  // symmetric (isup,jch) blocks per batch
#define NBLK 128

// per-(head,point) min as uint bits of nonneg float; reset to 0x7F7F7F7F
__device__ unsigned int g_minbits[HH * NPTS];
__device__ float g_partial[NBLK];

// ---- f32x2 helpers ---------------------------------------------------------
__device__ __forceinline__ unsigned long long pack2(float lo, float hi) {
    unsigned long long d;
    asm("mov.b64 %0, {%1, %2};" : "=l"(d) : "f"(lo), "f"(hi));
    return d;
}
__device__ __forceinline__ unsigned long long fma2(unsigned long long a,
                                                   unsigned long long b,
                                                   unsigned long long c) {
    unsigned long long d;
    asm("fma.rn.f32x2 %0, %1, %2, %3;" : "=l"(d) : "l"(a), "l"(b), "l"(c));
    return d;
}
__device__ __forceinline__ unsigned long long add2(unsigned long long a,
                                                   unsigned long long b) {
    unsigned long long d;
    asm("add.rn.f32x2 %0, %1, %2;" : "=l"(d) : "l"(a), "l"(b));
    return d;
}
__device__ __forceinline__ void unpack2(unsigned long long t, float& lo, float& hi) {
    asm("mov.b64 {%0, %1}, %2;" : "=f"(lo), "=f"(hi) : "l"(t));
}

// normalized plane normals + offset for batch b
__device__ __forceinline__ void load_normals(const float* __restrict__ planes,
                                             int b, float nx[HH], float ny[HH],
                                             float nz[HH], float nc[HH]) {
#pragma unroll
    for (int h = 0; h < HH; h++) {
        const float* pl = planes + (b * HH + h) * 4;
        float x = pl[0], y = pl[1], z = pl[2];
        float nn = x * x + y * y + z * z;
        float inv = rsqrtf(nn);
        inv = inv * (1.5f - 0.5f * nn * inv * inv);
        nx[h] = x * inv; ny[h] = y * inv; nz[h] = z * inv; nc[h] = pl[3];
    }
}

// ---------------------------------------------------------------------------
// Symmetric chamfer: block = (I-super 512 x J-chunk 256), jch >= 2*isup.
// v(p,q) = w_p + w_q - 2 p.q + 4 d_p d_q updates BOTH p's and q's min.
// I-mins in registers; J-mins in warp-private smem with rotating exclusive
// slot ownership (race-free). Overlap double-evals are idempotent under min.
// ---------------------------------------------------------------------------
__global__ __launch_bounds__(TP)
void chamfer_kernel(const float* __restrict__ planes,
                    const float* __restrict__ pts) {
    __shared__ ulonglong2         sA[NPAIR];   // (x0,x1),(y0,y1)
    __shared__ ulonglong2         sB[NPAIR];   // (z0,z1),(w0,w1)
    __shared__ ulonglong2         sC[NPAIR];   // (d0q0,d0q1),(d1q0,d1q1)
    __shared__ unsigned long long sD[NPAIR];   // (d2q0,d2q1)
    __shared__ float sJ[6][4][NPAIR];          // [head*2+half][warp][slot]

    const int t    = threadIdx.x;
    const int lane = t & 31;
    const int w    = t >> 5;
    const int b    = blockIdx.z;

    // decode (isup, jch): jch >= 2*isup, 72 blocks per batch
    int f = blockIdx.x, isup = 0;
    while (f >= 16 - 2 * isup) { f -= 16 - 2 * isup; isup++; }
    const int jch = 2 * isup + f;

    float nx[HH], ny[HH], nz[HH], nc[HH];
    load_normals(planes, b, nx, ny, nz, nc);

    // ---- stage J-chunk (one pair per thread) ----
    {
        const float* q = pts + (b * PP + jch * JCH + 2 * t) * 3;
        float x0 = q[0], y0 = q[1], z0 = q[2];
        float x1 = q[3], y1 = q[4], z1 = q[5];
        float w0 = x0 * x0 + y0 * y0 + z0 * z0;
        float w1 = x1 * x1 + y1 * y1 + z1 * z1;
        float d0[HH], d1[HH];
#pragma unroll
        for (int h = 0; h < HH; h++) {
            d0[h] = nx[h] * x0 + ny[h] * y0 + nz[h] * z0 + nc[h];
            d1[h] = nx[h] * x1 + ny[h] * y1 + nz[h] * z1 + nc[h];
        }
        ulonglong2 A, B, C;
        A.x = pack2(x0, x1);       A.y = pack2(y0, y1);
        B.x = pack2(z0, z1);       B.y = pack2(w0, w1);
        C.x = pack2(4.f * d0[0], 4.f * d1[0]);
        C.y = pack2(4.f * d0[1], 4.f * d1[1]);
        sA[t] = A; sB[t] = B; sC[t] = C;
        sD[t] = pack2(4.f * d0[2], 4.f * d1[2]);
    }
    // init J-min arrays
    for (int x = t; x < 6 * 4 * NPAIR; x += TP)
        (&sJ[0][0][0])[x] = CUDART_INF_F;

    // ---- I constants: IK points per thread, stride TP ----
    unsigned long long MX[IK], MY[IK], MZ[IK], WP[IK];
    unsigned long long Q0[IK], Q1[IK], Q2[IK];
    float im0[IK], im1[IK], im2[IK];
#pragma unroll
    for (int k = 0; k < IK; k++) {
        const int idx = b * PP + isup * ISUP + k * TP + t;
        const float* P = pts + idx * 3;
        float ax = P[0], ay = P[1], az = P[2];
        float e0 = nx[0] * ax + ny[0] * ay + nz[0] * az + nc[0];
        float e1 = nx[1] * ax + ny[1] * ay + nz[1] * az + nc[1];
        float e2 = nx[2] * ax + ny[2] * ay + nz[2] * az + nc[2];
        float wp = ax * ax + ay * ay + az * az;
        MX[k] = pack2(-2.f * ax, -2.f * ax);
        MY[k] = pack2(-2.f * ay, -2.f * ay);
        MZ[k] = pack2(-2.f * az, -2.f * az);
        WP[k] = pack2(wp, wp);
        Q0[k] = pack2(e0, e0);   // head scale 4 folded into J-side C/D
        Q1[k] = pack2(e1, e1);
        Q2[k] = pack2(e2, e2);
        im0[k] = im1[k] = im2[k] = CUDART_INF_F;
    }

    __syncthreads();

    // ---- main loop: rotating exclusive slot ownership ----
    for (int s2 = 0; s2 < 32; s2++) {
        const int base = (lane + s2) & 31;
#pragma unroll
        for (int sub = 0; sub < 4; sub++) {
            const int slot = sub * 32 + base;
            ulonglong2 A = sA[slot];
            ulonglong2 B = sB[slot];
            ulonglong2 C = sC[slot];
            unsigned long long D2 = sD[slot];

            float t00, t01, t10, t11, t20, t21;   // J-side trees
#pragma unroll
            for (int k = 0; k < IK; k++) {
                unsigned long long acc = fma2(MX[k], A.x, add2(B.y, WP[k]));
                acc = fma2(MY[k], A.y, acc);
                acc = fma2(MZ[k], B.x, acc);
                unsigned long long v0 = fma2(Q0[k], C.x, acc);
                unsigned long long v1 = fma2(Q1[k], C.y, acc);
                unsigned long long v2 = fma2(Q2[k], D2,  acc);
                float a0, b0, a1, b1, a2, b2;
                unpack2(v0, a0, b0);
                unpack2(v1, a1, b1);
                unpack2(v2, a2, b2);
                // I-side mins (full values, w_p already included)
                im0[k] = fminf(im0[k], fminf(a0, b0));
                im1[k] = fminf(im1[k], fminf(a1, b1));
                im2[k] = fminf(im2[k], fminf(a2, b2));
                // J-side trees
                if (k == 0) { t00 = a0; t01 = b0; t10 = a1; t11 = b1; t20 = a2; t21 = b2; }
                else {
                    t00 = fminf(t00, a0); t01 = fminf(t01, b0);
                    t10 = fminf(t10, a1); t11 = fminf(t11, b1);
                    t20 = fminf(t20, a2); t21 = fminf(t21, b2);
                }
            }
            // exclusive smem RMW (this lane owns these slots this rotation)
            sJ[0][w][slot] = fminf(sJ[0][w][slot], t00);
            sJ[1][w][slot] = fminf(sJ[1][w][slot], t01);
            sJ[2][w][slot] = fminf(sJ[2][w][slot], t10);
            sJ[3][w][slot] = fminf(sJ[3][w][slot], t11);
            sJ[4][w][slot] = fminf(sJ[4][w][slot], t20);
            sJ[5][w][slot] = fminf(sJ[5][w][slot], t21);
        }
        __syncwarp();
    }

    // ---- I-side epilogue ----
#pragma unroll
    for (int k = 0; k < IK; k++) {
        const int idx = b * PP + isup * ISUP + k * TP + t;
        atomicMin(&g_minbits[0 * NPTS + idx], __float_as_uint(fmaxf(im0[k], 0.f)));
        atomicMin(&g_minbits[1 * NPTS + idx], __float_as_uint(fmaxf(im1[k], 0.f)));
        atomicMin(&g_minbits[2 * NPTS + idx], __float_as_uint(fmaxf(im2[k], 0.f)));
    }

    __syncthreads();

    // ---- J-side merge: thread t owns slot t ----
    {
        const int j0 = b * PP + jch * JCH + 2 * t;
#pragma unroll
        for (int i = 0; i < 6; i++) {
            float m = fminf(fminf(sJ[i][0][t], sJ[i][1][t]),
                            fminf(sJ[i][2][t], sJ[i][3][t]));
            const int head = i >> 1, half = i & 1;
            atomicMin(&g_minbits[head * NPTS + j0 + half],
                      __float_as_uint(fmaxf(m, 0.f)));
        }
    }
}

// ---------------------------------------------------------------------------
// Combine: sum the 3 head-mins per point, deterministic block tree-reduce.
// ---------------------------------------------------------------------------
__global__ __launch_bounds__(256)
void combine_kernel() {
    __shared__ float red[256];
    const int i = blockIdx.x * 256 + threadIdx.x;

    float s = __uint_as_float(g_minbits[0 * NPTS + i])
            + __uint_as_float(g_minbits[1 * NPTS + i])
            + __uint_as_float(g_minbits[2 * NPTS + i]);

    red[threadIdx.x] = s;
    __syncthreads();
#pragma unroll
    for (int off = 128; off > 0; off >>= 1) {
        if (threadIdx.x < off) red[threadIdx.x] += red[threadIdx.x + off];
        __syncthreads();
    }
    if (threadIdx.x == 0) g_partial[blockIdx.x] = red[0];
}

// ---------------------------------------------------------------------------
// Finalize: tree-reduce partials + per-batch reg loss.
// ---------------------------------------------------------------------------
__global__ __launch_bounds__(128)
void finalize_kernel(const float* __restrict__ planes,
                     float* __restrict__ out) {
    __shared__ float red[128];
    __shared__ float regs[BB];
    const int t = threadIdx.x;

    red[t] = g_partial[t];
    __syncthreads();
#pragma unroll
    for (int off = 64; off > 0; off >>= 1) {
        if (t < off) red[t] += red[t + off];
        __syncthreads();
    }

    if (t < BB) {
        float nx[HH], ny[HH], nz[HH], nc[HH];
        load_normals(planes, t, nx, ny, nz, nc);
        float acc = 0.0f;
#pragma unroll
        for (int i = 0; i < HH; i++)
#pragma unroll
            for (int j = 0; j < HH; j++) {
                float g = nx[i] * nx[j] + ny[i] * ny[j] + nz[i] * nz[j]
                        - (i == j ? 1.0f : 0.0f);
                acc += g * g;
            }
        regs[t] = sqrtf(acc);
    }
    __syncthreads();

    if (t == 0) {
        float reg = 0.0f;
#pragma unroll
        for (int b = 0; b < BB; b++) reg += regs[b];
        float refl = 2.0f * red[0] / (float)(BB * PP);  // cham_x == cham_y
        out[0] = refl + 25.0f * reg;
    }
}

// ---------------------------------------------------------------------------
extern "C" void kernel_launch(void* const* d_in, const int* in_sizes, int n_in,
                              void* d_out, int out_size) {
    const float* planes = (const float*)d_in[0];   // (8, 3, 4)
    const float* pts    = (const float*)d_in[1];   // (8, 4096, 3)
    // d_in[2], d_in[3] unused by the reference.

    void* mb = nullptr;
    cudaGetSymbolAddress(&mb, g_minbits);
    cudaMemsetAsync(mb, 0x7F, (size_t)HH * NPTS * sizeof(unsigned int));

    dim3 grid(BLKB, 1, BB);   // 72 x 8 = 576 blocks
    chamfer_kernel<<<grid, TP>>>(planes, pts);

    combine_kernel<<<NBLK, 256>>>();
    finalize_kernel<<<1, 128>>>(planes, (float*)d_out);
}